// round 1
// baseline (speedup 1.0000x reference)
#include <cuda_runtime.h>
#include <cstdint>

#define NN 50000
#define EE 800000
#define RR 8
#define HH 128
#define LL 3
#define FDIM 6
#define KSUM (RR*HH)      // 1024
#define KTOT (KSUM+HH)    // 1152
#define BN_EPS 1e-5f

// ---------------- scratch (device globals: no allocation allowed) ----------
__device__ float  g_sums[(size_t)NN*RR*HH];   // per-(node,rel) feature sums
__device__ float  g_invcnt[NN*RR];
__device__ int    g_cnt[NN*RR];
__device__ float  g_W[KSUM*HH];               // per-layer basis-combined weights [r*H+i][o]
__device__ float  g_h[(size_t)NN*HH];         // pre-BN layer output
__device__ double g_bnsum[HH];
__device__ double g_bnss[HH];

// ---------------- kernels ---------------------------------------------------

// x0 = emb[ids] + relu(node_feat @ feat_w^T + feat_b) + virtual
__global__ void k_init_x(const int* __restrict__ ids, const float* __restrict__ nf,
                         const float* __restrict__ emb, const float* __restrict__ fw,
                         const float* __restrict__ fb, const float* __restrict__ virt,
                         float* __restrict__ x) {
    int i = blockIdx.x * blockDim.x + threadIdx.x;
    if (i >= NN*HH) return;
    int n = i >> 7, c = i & 127;
    float acc = fb[c];
#pragma unroll
    for (int f = 0; f < FDIM; f++) acc += nf[n*FDIM+f] * fw[c*FDIM+f];
    acc = fmaxf(acc, 0.f);
    x[i] = emb[(size_t)ids[n]*HH + c] + acc + virt[c];
}

__global__ void k_count(const int* __restrict__ ei, const int* __restrict__ et) {
    int e = blockIdx.x * blockDim.x + threadIdx.x;
    if (e >= EE) return;
    atomicAdd(&g_cnt[ei[EE+e]*RR + et[e]], 1);
}

__global__ void k_inv() {
    int i = blockIdx.x * blockDim.x + threadIdx.x;
    if (i >= NN*RR) return;
    g_invcnt[i] = 1.f / fmaxf((float)g_cnt[i], 1.f);
}

// W[r,i,o] = sum_b comp[l,r,b] * bases[l,b,i,o]   stored as g_W[(r*128+i)*128+o]
__global__ void k_makeW(const float* __restrict__ bases, const float* __restrict__ comp, int l) {
    int k = blockIdx.x;         // r*128 + i
    int o = threadIdx.x;
    int r = k >> 7, i = k & 127;
    const float* cp = comp + l*RR*8 + r*8;
    const float* bp = bases + (size_t)l*8*HH*HH + (size_t)i*HH + o;
    float acc = 0.f;
#pragma unroll
    for (int b = 0; b < 8; b++) acc += cp[b] * bp[(size_t)b*HH*HH];
    g_W[k*HH + o] = acc;
}

// one warp per edge: sums[(dst,rel)] += x[src]  (vector reduction, 4 floats/lane)
__global__ void k_agg(const int* __restrict__ ei, const int* __restrict__ et,
                      const float* __restrict__ x) {
    int wid  = (blockIdx.x * blockDim.x + threadIdx.x) >> 5;
    int lane = threadIdx.x & 31;
    if (wid >= EE) return;
    int src = ei[wid];
    int dst = ei[EE + wid];
    int t   = et[wid];
    float4 v = *reinterpret_cast<const float4*>(x + (size_t)src*HH + lane*4);
    float* p = g_sums + ((size_t)dst*RR + t)*HH + lane*4;
    asm volatile("red.global.add.v4.f32 [%0], {%1,%2,%3,%4};"
                 :: "l"(p), "f"(v.x), "f"(v.y), "f"(v.z), "f"(v.w) : "memory");
}

// h = [inv_cnt-scaled sums (K=1024) | x (K=128)] @ [W ; root_l] + bias_l
// also accumulates per-channel BN sum / sumsq (double atomics).
#define BM 64
#define BK 32
__global__ __launch_bounds__(256)
void k_gemm(const float* __restrict__ x, const float* __restrict__ root,
            const float* __restrict__ bias, int l) {
    __shared__ float As[BM*BK];
    __shared__ float Bs[BK*HH];
    __shared__ float invS[BM*RR];
    __shared__ float sb[HH];

    int tid = threadIdx.x;
    int n0  = blockIdx.x * BM;

    for (int i = tid; i < BM*RR; i += 256) {
        int row = i >> 3, r = i & 7, n = n0 + row;
        invS[i] = (n < NN) ? g_invcnt[n*RR + r] : 0.f;
    }
    if (tid < HH) sb[tid] = bias[l*HH + tid];

    float acc[8][4] = {};
    int tcol = (tid & 31) * 4;   // output column base (0..124)
    int trow = (tid >> 5) * 8;   // local row base   (0..56)
    const float* rootl = root + (size_t)l*HH*HH;

    // A-tile load mapping: 4 threads per row, 8 consecutive k each
    int arow = tid >> 2;
    int akb  = (tid & 3) * 8;
    // B-tile load mapping: 8 threads per k-row, 16 consecutive o each
    int bkrow = tid >> 3;
    int bob   = (tid & 7) * 16;

    for (int kt = 0; kt < KTOT/BK; kt++) {          // 36 tiles
        __syncthreads();
        { // load A (64 x 32), scaled by inv_cnt for the sums part
            int n = n0 + arow;
            float scale = 1.f;
            const float* sp;
            if (kt < KSUM/BK) {
                int k0 = kt * BK;
                scale = invS[arow*8 + (k0 >> 7)];
                sp = g_sums + (size_t)n*KSUM + k0 + akb;
            } else {
                int k0 = (kt - KSUM/BK) * BK;
                sp = x + (size_t)n*HH + k0 + akb;
            }
            float4 a0 = {0,0,0,0}, a1 = {0,0,0,0};
            if (n < NN) {
                a0 = *reinterpret_cast<const float4*>(sp);
                a1 = *reinterpret_cast<const float4*>(sp + 4);
            }
            float* d = As + arow*BK + akb;
            d[0]=a0.x*scale; d[1]=a0.y*scale; d[2]=a0.z*scale; d[3]=a0.w*scale;
            d[4]=a1.x*scale; d[5]=a1.y*scale; d[6]=a1.z*scale; d[7]=a1.w*scale;
        }
        { // load B (32 x 128)
            const float* bp;
            if (kt < KSUM/BK) bp = g_W  + (size_t)(kt*BK + bkrow)*HH + bob;
            else              bp = rootl + (size_t)((kt - KSUM/BK)*BK + bkrow)*HH + bob;
            float4* d = reinterpret_cast<float4*>(Bs + bkrow*HH + bob);
#pragma unroll
            for (int j = 0; j < 4; j++)
                d[j] = *reinterpret_cast<const float4*>(bp + j*4);
        }
        __syncthreads();
#pragma unroll
        for (int k = 0; k < BK; k++) {
            float4 bv = *reinterpret_cast<const float4*>(Bs + k*HH + tcol);
#pragma unroll
            for (int i = 0; i < 8; i++) {
                float a = As[(trow+i)*BK + k];
                acc[i][0] += a * bv.x;
                acc[i][1] += a * bv.y;
                acc[i][2] += a * bv.z;
                acc[i][3] += a * bv.w;
            }
        }
    }

    // epilogue: add bias, store h, accumulate BN partials
    float4 bb = *reinterpret_cast<const float4*>(sb + tcol);
    float ps[4] = {0,0,0,0}, pq[4] = {0,0,0,0};
#pragma unroll
    for (int i = 0; i < 8; i++) {
        int n = n0 + trow + i;
        if (n < NN) {
            float4 hv;
            hv.x = acc[i][0] + bb.x;
            hv.y = acc[i][1] + bb.y;
            hv.z = acc[i][2] + bb.z;
            hv.w = acc[i][3] + bb.w;
            *reinterpret_cast<float4*>(g_h + (size_t)n*HH + tcol) = hv;
            ps[0]+=hv.x; ps[1]+=hv.y; ps[2]+=hv.z; ps[3]+=hv.w;
            pq[0]+=hv.x*hv.x; pq[1]+=hv.y*hv.y; pq[2]+=hv.z*hv.z; pq[3]+=hv.w*hv.w;
        }
    }
#pragma unroll
    for (int j = 0; j < 4; j++) {
        atomicAdd(&g_bnsum[tcol+j], (double)ps[j]);
        atomicAdd(&g_bnss[tcol+j],  (double)pq[j]);
    }
}

// batchnorm + relu + residual (in place on x)
__global__ void k_bn(const float* __restrict__ gamma, const float* __restrict__ beta,
                     int l, float* __restrict__ x) {
    int i = blockIdx.x * blockDim.x + threadIdx.x;
    if (i >= NN*HH) return;
    int c = i & 127;
    double mu  = g_bnsum[c] / (double)NN;
    double var = g_bnss[c]  / (double)NN - mu*mu;
    float hv = g_h[i];
    float o  = gamma[l*HH+c] * (hv - (float)mu) * rsqrtf((float)var + BN_EPS) + beta[l*HH+c];
    x[i] += fmaxf(o, 0.f);
}

// ---------------- launch -----------------------------------------------------
extern "C" void kernel_launch(void* const* d_in, const int* in_sizes, int n_in,
                              void* d_out, int out_size) {
    const int*   x_ids = (const int*)  d_in[0];
    const int*   ei    = (const int*)  d_in[1];
    const int*   et    = (const int*)  d_in[2];
    const float* nf    = (const float*)d_in[3];
    const float* emb   = (const float*)d_in[4];
    const float* fw    = (const float*)d_in[5];
    const float* fb    = (const float*)d_in[6];
    const float* virt  = (const float*)d_in[7];
    const float* bases = (const float*)d_in[8];
    const float* comp  = (const float*)d_in[9];
    const float* root  = (const float*)d_in[10];
    const float* bias  = (const float*)d_in[11];
    const float* gamma = (const float*)d_in[12];
    const float* beta  = (const float*)d_in[13];
    float* x = (float*)d_out;

    void *p_cnt, *p_sums, *p_bnsum, *p_bnss;
    cudaGetSymbolAddress(&p_cnt,   g_cnt);
    cudaGetSymbolAddress(&p_sums,  g_sums);
    cudaGetSymbolAddress(&p_bnsum, g_bnsum);
    cudaGetSymbolAddress(&p_bnss,  g_bnss);

    cudaMemsetAsync(p_cnt, 0, sizeof(int)*NN*RR);
    k_init_x<<<(NN*HH + 255)/256, 256>>>(x_ids, nf, emb, fw, fb, virt, x);
    k_count <<<(EE + 255)/256, 256>>>(ei, et);
    k_inv   <<<(NN*RR + 255)/256, 256>>>();

    for (int l = 0; l < LL; l++) {
        k_makeW<<<KSUM, HH>>>(bases, comp, l);
        cudaMemsetAsync(p_sums, 0, sizeof(float)*(size_t)NN*RR*HH);
        k_agg<<<(EE*32 + 255)/256, 256>>>(ei, et, x);
        cudaMemsetAsync(p_bnsum, 0, sizeof(double)*HH);
        cudaMemsetAsync(p_bnss,  0, sizeof(double)*HH);
        k_gemm<<<(NN + BM - 1)/BM, 256>>>(x, root, bias, l);
        k_bn<<<(NN*HH + 255)/256, 256>>>(gamma, beta, l, x);
    }
}

// round 3
// speedup vs baseline: 1.8603x; 1.8603x over previous
#include <cuda_runtime.h>
#include <cstdint>

#define NN 50000
#define EE 800000
#define RR 8
#define HH 128
#define LL 3
#define FDIM 6
#define KALL 1152          // 8*128 relation cols + 128 root cols
#define NCT 36             // 1152/32 col-tiles
#define CTS_PER_GROUP 18
#define BN_EPS 1e-5f

// ---------------- scratch (device globals; no allocation allowed) -----------
__device__ float  g_xr[(size_t)NN*RR*HH];     // transformed features [N,1024]
__device__ float  g_h[(size_t)NN*HH];         // pre-BN layer output (prefilled x@root+bias)
__device__ float  g_invcnt[NN*RR];
__device__ int    g_cnt[NN*RR];
__device__ float  g_Wp[NCT*8192];             // permuted fragment-order weights (hi|lo per ct)
__device__ double g_bnsum[HH];
__device__ double g_bnss[HH];

// ---------------- helpers ----------------------------------------------------
__device__ __forceinline__ float tf32r(float x) {
    uint32_t u; asm("cvt.rna.tf32.f32 %0, %1;" : "=r"(u) : "f"(x));
    return __uint_as_float(u);
}
#define MMA_TF32(C, A0,A1,A2,A3, B0,B1) \
    asm volatile("mma.sync.aligned.m16n8k8.row.col.f32.tf32.tf32.f32 " \
        "{%0,%1,%2,%3},{%4,%5,%6,%7},{%8,%9},{%0,%1,%2,%3};" \
        : "+f"(C[0]),"+f"(C[1]),"+f"(C[2]),"+f"(C[3]) \
        : "r"(A0),"r"(A1),"r"(A2),"r"(A3),"r"(B0),"r"(B1))

__device__ __forceinline__ void cpasync16(uint32_t s, const void* g) {
    asm volatile("cp.async.cg.shared.global [%0], [%1], 16;" :: "r"(s), "l"(g));
}

// ---------------- kernels ---------------------------------------------------

// x0 = emb[ids] + relu(node_feat @ feat_w^T + feat_b) + virtual
__global__ void k_init_x(const int* __restrict__ ids, const float* __restrict__ nf,
                         const float* __restrict__ emb, const float* __restrict__ fw,
                         const float* __restrict__ fb, const float* __restrict__ virt,
                         float* __restrict__ x) {
    int i = blockIdx.x * blockDim.x + threadIdx.x;
    if (i >= NN*HH) return;
    int n = i >> 7, c = i & 127;
    float acc = fb[c];
#pragma unroll
    for (int f = 0; f < FDIM; f++) acc += nf[n*FDIM+f] * fw[c*FDIM+f];
    x[i] = emb[(size_t)ids[n]*HH + c] + fmaxf(acc, 0.f) + virt[c];
}

__global__ void k_count(const int* __restrict__ ei, const int* __restrict__ et) {
    int e = blockIdx.x * blockDim.x + threadIdx.x;
    if (e >= EE) return;
    atomicAdd(&g_cnt[ei[EE+e]*RR + et[e]], 1);
}

__global__ void k_inv() {
    int i = blockIdx.x * blockDim.x + threadIdx.x;
    if (i >= NN*RR) return;
    g_invcnt[i] = 1.f / fmaxf((float)g_cnt[i], 1.f);
}

// Build Wall[k, c] (c<1024: relation weights from bases; c>=1024: root), split
// into tf32 hi/lo, and scatter into fragment-order permuted layout g_Wp.
__global__ void k_makeWp(const float* __restrict__ bases, const float* __restrict__ comp,
                         const float* __restrict__ root, int l) {
    int idx = blockIdx.x * blockDim.x + threadIdx.x;
    if (idx >= HH*KALL) return;
    int k = idx / KALL, c = idx % KALL;
    float wv;
    if (c < 1024) {
        int r = c >> 7, o = c & 127;
        const float* cp = comp + (l*RR + r)*8;
        float acc = 0.f;
#pragma unroll
        for (int b = 0; b < 8; b++)
            acc += cp[b] * bases[(size_t)(((l*8 + b)*HH) + k)*HH + o];
        wv = acc;
    } else {
        wv = root[(size_t)(l*HH + k)*HH + (c - 1024)];
    }
    float hi = tf32r(wv);
    float lo = tf32r(wv - hi);
    // permuted index: ct slab 8192 floats = hi[16ks][4nt][32lane][2pr] then lo
    int ct = c >> 5, cin = c & 31;
    int nt = cin >> 3, nn = cin & 7;
    int ks = k >> 3, kin = k & 7;
    int tq = kin >> 1, pr = kin & 1;
    int lane = nn*4 + tq;
    int base = ct*8192 + (ks*4 + nt)*64 + lane*2 + pr;
    g_Wp[base]        = hi;
    g_Wp[base + 4096] = lo;
}

// 3xTF32 GEMM: [N,128] @ Wall[128,1152].  cols<1024 -> g_xr; cols>=1024 -> g_h (+bias)
// block: 128 rows x 576 cols (18 col-tiles of 32), 256 threads = 8 warps x 16 rows
__global__ __launch_bounds__(256)
void k_gemm(const float* __restrict__ x, const float* __restrict__ bias, int l) {
    extern __shared__ float sB[];   // 2 x 8192 floats (double-buffered ct slabs)
    int tid = threadIdx.x, w = tid >> 5, lane = tid & 31;
    int g = lane >> 2, t4 = lane & 3;
    int n0 = blockIdx.x * 128;
    int rA = n0 + w*16 + g, rB = rA + 8;
    bool vA = rA < NN, vB = rB < NN;
    int rAc = vA ? rA : NN-1, rBc = vB ? rB : NN-1;

    // Load A (full K=128) and split into tf32 hi/lo fragments: 128 regs
    uint32_t AH[16][4], AL[16][4];
#pragma unroll
    for (int ks = 0; ks < 16; ks++) {
        float2 a = *reinterpret_cast<const float2*>(x + (size_t)rAc*HH + ks*8 + 2*t4);
        float2 b = *reinterpret_cast<const float2*>(x + (size_t)rBc*HH + ks*8 + 2*t4);
        float h0 = tf32r(a.x), h2 = tf32r(a.y), h1 = tf32r(b.x), h3 = tf32r(b.y);
        AH[ks][0] = __float_as_uint(h0); AH[ks][1] = __float_as_uint(h1);
        AH[ks][2] = __float_as_uint(h2); AH[ks][3] = __float_as_uint(h3);
        AL[ks][0] = __float_as_uint(tf32r(a.x - h0));
        AL[ks][1] = __float_as_uint(tf32r(b.x - h1));
        AL[ks][2] = __float_as_uint(tf32r(a.y - h2));
        AL[ks][3] = __float_as_uint(tf32r(b.y - h3));
    }

    int ctbase = blockIdx.y * CTS_PER_GROUP;
    // prologue: prefetch slab 0
    {
        uint32_t sd = (uint32_t)__cvta_generic_to_shared(sB);
        const char* gs = (const char*)(g_Wp + (size_t)ctbase*8192);
#pragma unroll
        for (int j = 0; j < 8; j++)
            cpasync16(sd + (tid + j*256)*16, gs + (tid + j*256)*16);
        asm volatile("cp.async.commit_group;");
    }

    for (int i = 0; i < CTS_PER_GROUP; i++) {
        __syncthreads();                       // prev compute on other buffer done
        if (i < CTS_PER_GROUP-1) {
            uint32_t sd = (uint32_t)__cvta_generic_to_shared(sB + ((i+1)&1)*8192);
            const char* gs = (const char*)(g_Wp + (size_t)(ctbase+i+1)*8192);
#pragma unroll
            for (int j = 0; j < 8; j++)
                cpasync16(sd + (tid + j*256)*16, gs + (tid + j*256)*16);
            asm volatile("cp.async.commit_group;");
            asm volatile("cp.async.wait_group 1;");
        } else {
            asm volatile("cp.async.wait_group 0;");
        }
        __syncthreads();

        const float* B = sB + (i&1)*8192;
        float acc[4][4] = {};
#pragma unroll
        for (int ks = 0; ks < 16; ks++) {
#pragma unroll
            for (int nt = 0; nt < 4; nt++) {
                float2 bh = *reinterpret_cast<const float2*>(B + (ks*4+nt)*64 + lane*2);
                float2 bl = *reinterpret_cast<const float2*>(B + 4096 + (ks*4+nt)*64 + lane*2);
                uint32_t bh0 = __float_as_uint(bh.x), bh1 = __float_as_uint(bh.y);
                uint32_t bl0 = __float_as_uint(bl.x), bl1 = __float_as_uint(bl.y);
                MMA_TF32(acc[nt], AH[ks][0],AH[ks][1],AH[ks][2],AH[ks][3], bh0,bh1);
                MMA_TF32(acc[nt], AH[ks][0],AH[ks][1],AH[ks][2],AH[ks][3], bl0,bl1);
                MMA_TF32(acc[nt], AL[ks][0],AL[ks][1],AL[ks][2],AL[ks][3], bh0,bh1);
            }
        }
        // epilogue
        int ct = ctbase + i;
        if (ct < 32) {
#pragma unroll
            for (int nt = 0; nt < 4; nt++) {
                int col = ct*32 + nt*8 + 2*t4;
                if (vA) *reinterpret_cast<float2*>(g_xr + (size_t)rA*1024 + col) =
                        make_float2(acc[nt][0], acc[nt][1]);
                if (vB) *reinterpret_cast<float2*>(g_xr + (size_t)rB*1024 + col) =
                        make_float2(acc[nt][2], acc[nt][3]);
            }
        } else {
#pragma unroll
            for (int nt = 0; nt < 4; nt++) {
                int o = ct*32 - 1024 + nt*8 + 2*t4;
                float b0 = bias[l*HH + o], b1 = bias[l*HH + o + 1];
                if (vA) *reinterpret_cast<float2*>(g_h + (size_t)rA*HH + o) =
                        make_float2(acc[nt][0] + b0, acc[nt][1] + b1);
                if (vB) *reinterpret_cast<float2*>(g_h + (size_t)rB*HH + o) =
                        make_float2(acc[nt][2] + b0, acc[nt][3] + b1);
            }
        }
    }
}

// one warp per edge: h[dst] += inv_cnt[dst,et] * xr[src, et]
__global__ void k_agg(const int* __restrict__ ei, const int* __restrict__ et) {
    int wid  = (blockIdx.x * blockDim.x + threadIdx.x) >> 5;
    int lane = threadIdx.x & 31;
    if (wid >= EE) return;
    int src = ei[wid];
    int dst = ei[EE + wid];
    int t   = et[wid];
    float s = g_invcnt[dst*RR + t];
    float4 v = *reinterpret_cast<const float4*>(g_xr + (size_t)src*1024 + t*HH + lane*4);
    float* p = g_h + (size_t)dst*HH + lane*4;
    asm volatile("red.global.add.v4.f32 [%0], {%1,%2,%3,%4};"
                 :: "l"(p), "f"(v.x*s), "f"(v.y*s), "f"(v.z*s), "f"(v.w*s) : "memory");
}

// per-channel BN statistics over g_h
__global__ void k_bnstat() {
    int c = threadIdx.x;                 // 128 threads
    int r0 = blockIdx.x * 125;           // 400 blocks x 125 rows
    float s = 0.f, q = 0.f;
    for (int r = r0; r < r0 + 125; r++) {
        float v = g_h[(size_t)r*HH + c];
        s += v; q += v*v;
    }
    atomicAdd(&g_bnsum[c], (double)s);
    atomicAdd(&g_bnss[c],  (double)q);
}

// batchnorm + relu + residual (in place on x)
__global__ void k_bn(const float* __restrict__ gamma, const float* __restrict__ beta,
                     int l, float* __restrict__ x) {
    int i = blockIdx.x * blockDim.x + threadIdx.x;
    if (i >= NN*HH) return;
    int c = i & 127;
    double mu  = g_bnsum[c] / (double)NN;
    double var = g_bnss[c]  / (double)NN - mu*mu;
    float hv = g_h[i];
    float o  = gamma[l*HH+c] * (hv - (float)mu) * rsqrtf((float)var + BN_EPS) + beta[l*HH+c];
    x[i] += fmaxf(o, 0.f);
}

// ---------------- launch -----------------------------------------------------
extern "C" void kernel_launch(void* const* d_in, const int* in_sizes, int n_in,
                              void* d_out, int out_size) {
    const int*   x_ids = (const int*)  d_in[0];
    const int*   ei    = (const int*)  d_in[1];
    const int*   et    = (const int*)  d_in[2];
    const float* nf    = (const float*)d_in[3];
    const float* emb   = (const float*)d_in[4];
    const float* fw    = (const float*)d_in[5];
    const float* fb    = (const float*)d_in[6];
    const float* virt  = (const float*)d_in[7];
    const float* bases = (const float*)d_in[8];
    const float* comp  = (const float*)d_in[9];
    const float* root  = (const float*)d_in[10];
    const float* bias  = (const float*)d_in[11];
    const float* gamma = (const float*)d_in[12];
    const float* beta  = (const float*)d_in[13];
    float* x = (float*)d_out;

    static bool attr_set = false;
    if (!attr_set) {
        cudaFuncSetAttribute(k_gemm, cudaFuncAttributeMaxDynamicSharedMemorySize, 65536);
        attr_set = true;
    }

    void *p_cnt, *p_bnsum, *p_bnss;
    cudaGetSymbolAddress(&p_cnt,   g_cnt);
    cudaGetSymbolAddress(&p_bnsum, g_bnsum);
    cudaGetSymbolAddress(&p_bnss,  g_bnss);

    cudaMemsetAsync(p_cnt, 0, sizeof(int)*NN*RR);
    k_init_x<<<(NN*HH + 255)/256, 256>>>(x_ids, nf, emb, fw, fb, virt, x);
    k_count <<<(EE + 255)/256, 256>>>(ei, et);
    k_inv   <<<(NN*RR + 255)/256, 256>>>();

    dim3 ggrid((NN + 127)/128, 2);
    for (int l = 0; l < LL; l++) {
        k_makeWp<<<(HH*KALL + 255)/256, 256>>>(bases, comp, root, l);
        k_gemm<<<ggrid, 256, 65536>>>(x, bias, l);
        k_agg<<<(EE*32 + 255)/256, 256>>>(ei, et);
        cudaMemsetAsync(p_bnsum, 0, sizeof(double)*HH);
        cudaMemsetAsync(p_bnss,  0, sizeof(double)*HH);
        k_bnstat<<<400, 128>>>();
        k_bn<<<(NN*HH + 255)/256, 256>>>(gamma, beta, l, x);
    }
}